// round 1
// baseline (speedup 1.0000x reference)
#include <cuda_runtime.h>
#include <math.h>

// Problem constants (fixed shapes for this instance)
#define B_ 8
#define L_ 4096
#define D_ 2048
#define H_ 16
#define HD_ 128
#define NCHUNK 8
#define CHUNK (L_ / NCHUNK)   // 512
#define NWARP 4

// Scratch (device globals — no allocation allowed)
__device__ float g_qkv[3 * B_ * D_];          // q, k, v after projection (+RoPE in-place)
__device__ float g_pm[B_ * H_ * NCHUNK];      // partial max
__device__ float g_pl[B_ * H_ * NCHUNK];      // partial sum
__device__ float g_pacc[B_ * H_ * NCHUNK * HD_]; // partial weighted V accum
__device__ float g_attn[B_ * D_];             // attention output before Wo

// ---------------------------------------------------------------------------
// Zero scratch + d_out (atomics accumulate into both)
// ---------------------------------------------------------------------------
__global__ void zero_kernel(float* __restrict__ out) {
    int idx = blockIdx.x * 256 + threadIdx.x;
    if (idx < 3 * B_ * D_) g_qkv[idx] = 0.0f;
    if (idx < B_ * D_) out[idx] = 0.0f;
}

// ---------------------------------------------------------------------------
// Split-K GEMM: out[z] += A(8x2048) @ W[z](2048x2048)
// grid (16 j-chunks, 16 i-chunks, nz), block 128
// ---------------------------------------------------------------------------
__global__ void gemm_kernel(const float* __restrict__ A,
                            const float* __restrict__ W0,
                            const float* __restrict__ W1,
                            const float* __restrict__ W2,
                            float* __restrict__ out) {
    const float* W = (blockIdx.z == 0) ? W0 : ((blockIdx.z == 1) ? W1 : W2);
    float* o = out + blockIdx.z * (B_ * D_);

    __shared__ float xs[B_][128];
    int tid = threadIdx.x;
    int i0 = blockIdx.y * 128;
    for (int t = tid; t < B_ * 128; t += 128) {
        int b = t >> 7, i = t & 127;
        xs[b][i] = A[b * D_ + i0 + i];
    }
    __syncthreads();

    int j = blockIdx.x * 128 + tid;
    float acc[B_];
#pragma unroll
    for (int b = 0; b < B_; b++) acc[b] = 0.0f;

    const float* Wp = W + (long)i0 * D_ + j;
#pragma unroll 8
    for (int i = 0; i < 128; i++) {
        float w = Wp[(long)i * D_];
#pragma unroll
        for (int b = 0; b < B_; b++) acc[b] += xs[b][i] * w;
    }
#pragma unroll
    for (int b = 0; b < B_; b++) atomicAdd(&o[b * D_ + j], acc[b]);
}

// ---------------------------------------------------------------------------
// RoPE at position 4096 (s=1). In-place on q (z=0) and k (z=1).
// grid (H_, B_, 2), block 64
// ---------------------------------------------------------------------------
__global__ void rope_kernel() {
    int d = threadIdx.x;            // 0..63
    int h = blockIdx.x, b = blockIdx.y, m = blockIdx.z;
    float* t = g_qkv + m * (B_ * D_) + b * D_ + h * HD_;
    double inv = pow(10000.0, -(double)d / 64.0);
    double ang = 4096.0 * inv;
    float c = (float)cos(ang), s = (float)sin(ang);
    float x1 = t[d], x2 = t[d + 64];
    t[d]      = x1 * c - x2 * s;
    t[d + 64] = x1 * s + x2 * c;
}

// ---------------------------------------------------------------------------
// Flash-decode partial: each block handles one (chunk, head, batch).
// Each warp scans keys stride-NWARP; lane owns 4 head dims (float4).
// grid (NCHUNK, H_, B_), block 128 (4 warps)
// ---------------------------------------------------------------------------
__global__ void attn_partial(const float* __restrict__ kc,
                             const float* __restrict__ vc) {
    int c = blockIdx.x, h = blockIdx.y, b = blockIdx.z;
    int tid = threadIdx.x, w = tid >> 5, lane = tid & 31;

    __shared__ float qs[HD_];
    __shared__ float sm_m[NWARP], sm_l[NWARP];
    __shared__ float sm_acc[NWARP][HD_];

    const float scale = 0.08838834764831845f;  // 1/sqrt(128)
    qs[tid] = g_qkv[b * D_ + h * HD_ + tid] * scale;
    __syncthreads();

    float4 qv = *(const float4*)&qs[lane * 4];

    float m = -1e30f, l = 0.0f;
    float4 acc = make_float4(0.f, 0.f, 0.f, 0.f);

    const float* kbase = kc + ((long)b * L_ * H_ + h) * HD_;
    const float* vbase = vc + ((long)b * L_ * H_ + h) * HD_;

    for (int kk = w; kk < CHUNK; kk += NWARP) {
        long pos = (long)(c * CHUNK + kk) * (H_ * HD_);
        float4 kd = *(const float4*)(kbase + pos + lane * 4);
        float4 vd = *(const float4*)(vbase + pos + lane * 4);

        float s = qv.x * kd.x + qv.y * kd.y + qv.z * kd.z + qv.w * kd.w;
        s += __shfl_xor_sync(0xFFFFFFFFu, s, 16);
        s += __shfl_xor_sync(0xFFFFFFFFu, s, 8);
        s += __shfl_xor_sync(0xFFFFFFFFu, s, 4);
        s += __shfl_xor_sync(0xFFFFFFFFu, s, 2);
        s += __shfl_xor_sync(0xFFFFFFFFu, s, 1);

        float mn = fmaxf(m, s);
        float f = __expf(m - mn);
        float p = __expf(s - mn);
        m = mn;
        l = l * f + p;
        acc.x = acc.x * f + p * vd.x;
        acc.y = acc.y * f + p * vd.y;
        acc.z = acc.z * f + p * vd.z;
        acc.w = acc.w * f + p * vd.w;
    }

    if (lane == 0) { sm_m[w] = m; sm_l[w] = l; }
    *(float4*)&sm_acc[w][lane * 4] = acc;
    __syncthreads();

    if (w == 0) {
        float bm = fmaxf(fmaxf(sm_m[0], sm_m[1]), fmaxf(sm_m[2], sm_m[3]));
        float bl = 0.0f;
        float4 ba = make_float4(0.f, 0.f, 0.f, 0.f);
#pragma unroll
        for (int i = 0; i < NWARP; i++) {
            float f = __expf(sm_m[i] - bm);
            bl += sm_l[i] * f;
            float4 a = *(float4*)&sm_acc[i][lane * 4];
            ba.x += a.x * f; ba.y += a.y * f; ba.z += a.z * f; ba.w += a.w * f;
        }
        int pidx = (b * H_ + h) * NCHUNK + c;
        if (lane == 0) { g_pm[pidx] = bm; g_pl[pidx] = bl; }
        *(float4*)&g_pacc[pidx * HD_ + lane * 4] = ba;
    }
}

// ---------------------------------------------------------------------------
// Combine chunk partials + new-token contribution (pos 4096, always visible).
// grid (H_, B_), block 128 (thread d owns dim d)
// ---------------------------------------------------------------------------
__global__ void attn_combine() {
    int h = blockIdx.x, b = blockIdx.y, d = threadIdx.x;
    const float scale = 0.08838834764831845f;

    __shared__ float red[HD_];
    float qd = g_qkv[b * D_ + h * HD_ + d];
    float kn = g_qkv[B_ * D_ + b * D_ + h * HD_ + d];
    red[d] = qd * kn;
    __syncthreads();
    for (int st = 64; st > 0; st >>= 1) {
        if (d < st) red[d] += red[d + st];
        __syncthreads();
    }
    float s_new = red[0] * scale;

    float pm[NCHUNK], pl[NCHUNK];
    float M = s_new;
    int base = (b * H_ + h) * NCHUNK;
#pragma unroll
    for (int i = 0; i < NCHUNK; i++) {
        pm[i] = g_pm[base + i];
        pl[i] = g_pl[base + i];
        M = fmaxf(M, pm[i]);
    }
    float pn = __expf(s_new - M);
    float L = pn;
    float o = pn * g_qkv[2 * B_ * D_ + b * D_ + h * HD_ + d];  // v_new
#pragma unroll
    for (int i = 0; i < NCHUNK; i++) {
        float f = __expf(pm[i] - M);
        L += pl[i] * f;
        o += f * g_pacc[(base + i) * HD_ + d];
    }
    g_attn[b * D_ + h * HD_ + d] = o / L;
}

// ---------------------------------------------------------------------------
// Launch
// ---------------------------------------------------------------------------
extern "C" void kernel_launch(void* const* d_in, const int* in_sizes, int n_in,
                              void* d_out, int out_size) {
    const float* x  = (const float*)d_in[0];
    const float* kc = (const float*)d_in[1];
    const float* vc = (const float*)d_in[2];
    const float* Wq = (const float*)d_in[3];
    const float* Wk = (const float*)d_in[4];
    const float* Wv = (const float*)d_in[5];
    const float* Wo = (const float*)d_in[6];
    float* out = (float*)d_out;

    float* g_qkv_p;  cudaGetSymbolAddress((void**)&g_qkv_p, g_qkv);
    float* g_attn_p; cudaGetSymbolAddress((void**)&g_attn_p, g_attn);

    // 1. zero scratch + output
    zero_kernel<<<(3 * B_ * D_ + 255) / 256, 256>>>(out);

    // 2. q,k,v = x @ {Wq,Wk,Wv}
    gemm_kernel<<<dim3(D_ / 128, D_ / 128, 3), 128>>>(x, Wq, Wk, Wv, g_qkv_p);

    // 3. RoPE on q and k at pos=4096
    rope_kernel<<<dim3(H_, B_, 2), 64>>>();

    // 4. flash-decode partials over the 4096-entry cache
    attn_partial<<<dim3(NCHUNK, H_, B_), 128>>>(kc, vc);

    // 5. combine partials + new token
    attn_combine<<<dim3(H_, B_), HD_>>>();

    // 6. out = attn @ Wo
    gemm_kernel<<<dim3(D_ / 128, D_ / 128, 1), 128>>>(g_attn_p, Wo, Wo, Wo, out);
}

// round 2
// speedup vs baseline: 1.0402x; 1.0402x over previous
#include <cuda_runtime.h>
#include <math.h>

// Problem constants (fixed shapes for this instance)
#define B_ 8
#define L_ 4096
#define D_ 2048
#define H_ 16
#define HD_ 128
#define NCHUNK 16
#define CHUNK (L_ / NCHUNK)   // 256
#define NWARP 4

// Scratch (device globals — no allocation allowed)
__device__ float g_qkv[3 * B_ * D_];             // q, k, v after projection (+RoPE in-place)
__device__ float g_pm[B_ * H_ * NCHUNK];         // partial max
__device__ float g_pl[B_ * H_ * NCHUNK];         // partial sum
__device__ float g_pacc[B_ * H_ * NCHUNK * HD_]; // partial weighted V accum
__device__ float g_attn[B_ * D_];                // attention output before Wo

// ---------------------------------------------------------------------------
// Zero scratch + d_out (atomics accumulate into both)
// ---------------------------------------------------------------------------
__global__ void zero_kernel(float* __restrict__ out) {
    int idx = blockIdx.x * 256 + threadIdx.x;
    if (idx < 3 * B_ * D_) g_qkv[idx] = 0.0f;
    if (idx < B_ * D_) out[idx] = 0.0f;
}

// ---------------------------------------------------------------------------
// Split-K GEMM: out[z] += A(8x2048) @ W[z](2048x2048)
// grid (16 j-chunks, 16 i-chunks, nz), block 128
// ---------------------------------------------------------------------------
__global__ void gemm_kernel(const float* __restrict__ A,
                            const float* __restrict__ W0,
                            const float* __restrict__ W1,
                            const float* __restrict__ W2,
                            float* __restrict__ out) {
    const float* W = (blockIdx.z == 0) ? W0 : ((blockIdx.z == 1) ? W1 : W2);
    float* o = out + blockIdx.z * (B_ * D_);

    __shared__ float xs[B_][128];
    int tid = threadIdx.x;
    int i0 = blockIdx.y * 128;
    for (int t = tid; t < B_ * 128; t += 128) {
        int b = t >> 7, i = t & 127;
        xs[b][i] = A[b * D_ + i0 + i];
    }
    __syncthreads();

    int j = blockIdx.x * 128 + tid;
    float acc[B_];
#pragma unroll
    for (int b = 0; b < B_; b++) acc[b] = 0.0f;

    const float* Wp = W + (long)i0 * D_ + j;
#pragma unroll 16
    for (int i = 0; i < 128; i++) {
        float w = Wp[(long)i * D_];
#pragma unroll
        for (int b = 0; b < B_; b++) acc[b] += xs[b][i] * w;
    }
#pragma unroll
    for (int b = 0; b < B_; b++) atomicAdd(&o[b * D_ + j], acc[b]);
}

// ---------------------------------------------------------------------------
// RoPE at position 4096 (s=1). In-place on q (z=0) and k (z=1).
// grid (H_, B_, 2), block 64
// ---------------------------------------------------------------------------
__global__ void rope_kernel() {
    int d = threadIdx.x;            // 0..63
    int h = blockIdx.x, b = blockIdx.y, m = blockIdx.z;
    float* t = g_qkv + m * (B_ * D_) + b * D_ + h * HD_;
    double inv = pow(10000.0, -(double)d / 64.0);
    double ang = 4096.0 * inv;
    float c = (float)cos(ang), s = (float)sin(ang);
    float x1 = t[d], x2 = t[d + 64];
    t[d]      = x1 * c - x2 * s;
    t[d + 64] = x1 * s + x2 * c;
}

// ---------------------------------------------------------------------------
// Flash-decode partial: each block handles one (chunk, head, batch).
// Warp w owns key pairs {base, base+1} with base = c*CHUNK + w*2 + it*8.
// Lane owns 4 head dims (float4). 2-key unroll -> 4 independent 512B row
// loads in flight per warp per iteration, one softmax renorm per 2 keys.
// grid (NCHUNK, H_, B_), block 128 (4 warps)
// ---------------------------------------------------------------------------
__global__ void attn_partial(const float* __restrict__ kc,
                             const float* __restrict__ vc) {
    int c = blockIdx.x, h = blockIdx.y, b = blockIdx.z;
    int tid = threadIdx.x, w = tid >> 5, lane = tid & 31;

    __shared__ float qs[HD_];
    __shared__ float sm_m[NWARP], sm_l[NWARP];
    __shared__ float sm_acc[NWARP][HD_];

    const float scale = 0.08838834764831845f;  // 1/sqrt(128)
    qs[tid] = g_qkv[b * D_ + h * HD_ + tid] * scale;
    __syncthreads();

    float4 qv = *(const float4*)&qs[lane * 4];

    float m = -1e30f, l = 0.0f;
    float4 acc = make_float4(0.f, 0.f, 0.f, 0.f);

    const long ROWSTRIDE = (long)H_ * HD_;
    const float* kp = kc + ((long)b * L_ * H_ + h) * HD_
                         + (long)(c * CHUNK + w * 2) * ROWSTRIDE + lane * 4;
    const float* vp = vc + ((long)b * L_ * H_ + h) * HD_
                         + (long)(c * CHUNK + w * 2) * ROWSTRIDE + lane * 4;

#pragma unroll 4
    for (int it = 0; it < CHUNK / (NWARP * 2); it++) {
        long off = (long)it * (NWARP * 2) * ROWSTRIDE;
        float4 k0 = *(const float4*)(kp + off);
        float4 k1 = *(const float4*)(kp + off + ROWSTRIDE);
        float4 v0 = *(const float4*)(vp + off);
        float4 v1 = *(const float4*)(vp + off + ROWSTRIDE);

        float s0 = qv.x * k0.x + qv.y * k0.y + qv.z * k0.z + qv.w * k0.w;
        float s1 = qv.x * k1.x + qv.y * k1.y + qv.z * k1.z + qv.w * k1.w;
#pragma unroll
        for (int st = 16; st > 0; st >>= 1) {
            s0 += __shfl_xor_sync(0xFFFFFFFFu, s0, st);
            s1 += __shfl_xor_sync(0xFFFFFFFFu, s1, st);
        }

        float mn = fmaxf(m, fmaxf(s0, s1));
        float f  = __expf(m - mn);
        float p0 = __expf(s0 - mn);
        float p1 = __expf(s1 - mn);
        m = mn;
        l = l * f + p0 + p1;
        acc.x = acc.x * f + p0 * v0.x + p1 * v1.x;
        acc.y = acc.y * f + p0 * v0.y + p1 * v1.y;
        acc.z = acc.z * f + p0 * v0.z + p1 * v1.z;
        acc.w = acc.w * f + p0 * v0.w + p1 * v1.w;
    }

    if (lane == 0) { sm_m[w] = m; sm_l[w] = l; }
    *(float4*)&sm_acc[w][lane * 4] = acc;
    __syncthreads();

    if (w == 0) {
        float bm = fmaxf(fmaxf(sm_m[0], sm_m[1]), fmaxf(sm_m[2], sm_m[3]));
        float bl = 0.0f;
        float4 ba = make_float4(0.f, 0.f, 0.f, 0.f);
#pragma unroll
        for (int i = 0; i < NWARP; i++) {
            float f = __expf(sm_m[i] - bm);
            bl += sm_l[i] * f;
            float4 a = *(float4*)&sm_acc[i][lane * 4];
            ba.x += a.x * f; ba.y += a.y * f; ba.z += a.z * f; ba.w += a.w * f;
        }
        int pidx = (b * H_ + h) * NCHUNK + c;
        if (lane == 0) { g_pm[pidx] = bm; g_pl[pidx] = bl; }
        *(float4*)&g_pacc[pidx * HD_ + lane * 4] = ba;
    }
}

// ---------------------------------------------------------------------------
// Combine chunk partials + new-token contribution (pos 4096, always visible).
// grid (H_, B_), block 128 (thread d owns dim d)
// ---------------------------------------------------------------------------
__global__ void attn_combine() {
    int h = blockIdx.x, b = blockIdx.y, d = threadIdx.x;
    const float scale = 0.08838834764831845f;

    __shared__ float red[HD_];
    float qd = g_qkv[b * D_ + h * HD_ + d];
    float kn = g_qkv[B_ * D_ + b * D_ + h * HD_ + d];
    red[d] = qd * kn;
    __syncthreads();
    for (int st = 64; st > 0; st >>= 1) {
        if (d < st) red[d] += red[d + st];
        __syncthreads();
    }
    float s_new = red[0] * scale;

    float pm[NCHUNK], pl[NCHUNK];
    float M = s_new;
    int base = (b * H_ + h) * NCHUNK;
#pragma unroll
    for (int i = 0; i < NCHUNK; i++) {
        pm[i] = g_pm[base + i];
        pl[i] = g_pl[base + i];
        M = fmaxf(M, pm[i]);
    }
    float pn = __expf(s_new - M);
    float L = pn;
    float o = pn * g_qkv[2 * B_ * D_ + b * D_ + h * HD_ + d];  // v_new
#pragma unroll
    for (int i = 0; i < NCHUNK; i++) {
        float f = __expf(pm[i] - M);
        L += pl[i] * f;
        o += f * g_pacc[(base + i) * HD_ + d];
    }
    g_attn[b * D_ + h * HD_ + d] = o / L;
}

// ---------------------------------------------------------------------------
// Launch
// ---------------------------------------------------------------------------
extern "C" void kernel_launch(void* const* d_in, const int* in_sizes, int n_in,
                              void* d_out, int out_size) {
    const float* x  = (const float*)d_in[0];
    const float* kc = (const float*)d_in[1];
    const float* vc = (const float*)d_in[2];
    const float* Wq = (const float*)d_in[3];
    const float* Wk = (const float*)d_in[4];
    const float* Wv = (const float*)d_in[5];
    const float* Wo = (const float*)d_in[6];
    float* out = (float*)d_out;

    float* g_qkv_p;  cudaGetSymbolAddress((void**)&g_qkv_p, g_qkv);
    float* g_attn_p; cudaGetSymbolAddress((void**)&g_attn_p, g_attn);

    // 1. zero scratch + output
    zero_kernel<<<(3 * B_ * D_ + 255) / 256, 256>>>(out);

    // 2. q,k,v = x @ {Wq,Wk,Wv}
    gemm_kernel<<<dim3(D_ / 128, D_ / 128, 3), 128>>>(x, Wq, Wk, Wv, g_qkv_p);

    // 3. RoPE on q and k at pos=4096
    rope_kernel<<<dim3(H_, B_, 2), 64>>>();

    // 4. flash-decode partials over the 4096-entry cache
    attn_partial<<<dim3(NCHUNK, H_, B_), 128>>>(kc, vc);

    // 5. combine partials + new token
    attn_combine<<<dim3(H_, B_), HD_>>>();

    // 6. out = attn @ Wo
    gemm_kernel<<<dim3(D_ / 128, D_ / 128, 1), 128>>>(g_attn_p, Wo, Wo, Wo, out);
}